// round 14
// baseline (speedup 1.0000x reference)
#include <cuda_runtime.h>
#include <cuda_fp16.h>
#include <cstdint>
#include <math.h>

#define D_H   128
#define D_E   64
#define F0    320
#define H1    256
#define H2    128
#define MAX_NODES 50000
#define MAX_EDGES 800000

// ======================= helpers ==================================================
__device__ __forceinline__ uint32_t smem_to_u32(const void* p) {
    uint32_t a;
    asm("{ .reg .u64 t; cvta.to.shared.u64 t, %1; cvt.u32.u64 %0, t; }" : "=r"(a) : "l"(p));
    return a;
}
#define SWZ(off) ((off) ^ (((off) >> 3) & 0x70))

__device__ __forceinline__ void ldsm4(uint32_t* r, uint32_t addr) {
    asm volatile("ldmatrix.sync.aligned.m8n8.x4.shared.b16 {%0,%1,%2,%3}, [%4];"
                 : "=r"(r[0]), "=r"(r[1]), "=r"(r[2]), "=r"(r[3]) : "r"(addr));
}
__device__ __forceinline__ void mma_f16(float* d, const uint32_t* a, uint32_t b0, uint32_t b1) {
    asm volatile("mma.sync.aligned.m16n8k16.row.col.f32.f16.f16.f32 "
                 "{%0,%1,%2,%3}, {%4,%5,%6,%7}, {%8,%9}, {%0,%1,%2,%3};"
                 : "+f"(d[0]), "+f"(d[1]), "+f"(d[2]), "+f"(d[3])
                 : "r"(a[0]), "r"(a[1]), "r"(a[2]), "r"(a[3]), "r"(b0), "r"(b1));
}
__device__ __forceinline__ void split_pair_h(float x, float y, uint32_t& hi, uint32_t& lo) {
    __half2 h = __floats2half2_rn(x, y);
    float2 hf = __half22float2(h);
    __half2 l = __floats2half2_rn(x - hf.x, y - hf.y);
    hi = *reinterpret_cast<uint32_t*>(&h);
    lo = *reinterpret_cast<uint32_t*>(&l);
}
__device__ __forceinline__ void cp16(uint32_t smem_dst, const void* gmem_src) {
    asm volatile("cp.async.ca.shared.global [%0], [%1], 16;"
                 :: "r"(smem_dst), "l"(gmem_src));
}
#define CP_COMMIT() asm volatile("cp.async.commit_group;" ::: "memory")
#define CP_WAIT1()  asm volatile("cp.async.wait_group 1;" ::: "memory")
#define CP_WAIT0()  asm volatile("cp.async.wait_group 0;" ::: "memory")

// ======================= device scratch ==========================================
__device__ __half g_h2h[(size_t)MAX_NODES * D_H];   // pre-split h planes
__device__ __half g_h2l[(size_t)MAX_NODES * D_H];
__device__ __half g_e2h[(size_t)MAX_EDGES * D_E];   // pre-split e planes
__device__ __half g_e2l[(size_t)MAX_EDGES * D_E];
__device__ __half g_y1h[(size_t)MAX_EDGES * H1];
__device__ __half g_y1l[(size_t)MAX_EDGES * H1];
__device__ float  g_y2f[(size_t)MAX_EDGES * H2];
__device__ __half g_W1h[H1 * F0];
__device__ __half g_W2h[H2 * H1];
__device__ int   g_cnt_src[MAX_NODES];
__device__ int   g_cnt_dst[MAX_NODES];
__device__ float g_sum0[F0], g_sq0[F0];
__device__ float g_sum1[H1], g_sq1[H1];
__device__ float g_sum2[H2], g_sq2[H2];
__device__ float g_scale0[F0], g_shift0[F0];
__device__ float g_scale1[H1], g_shift1[H1];
__device__ float g_scale2[H2], g_shift2[H2];
__device__ float g_b1f[H1], g_b2f[H2];
__device__ float g_W3f[H2];
__device__ float g_b3f[1];

// ======================= setup / stats kernels ===================================
__global__ void zero_kernel(int n_nodes) {
    int i = blockIdx.x * blockDim.x + threadIdx.x;
    if (i < n_nodes) { g_cnt_src[i] = 0; g_cnt_dst[i] = 0; }
    if (i < F0) { g_sum0[i] = 0.f; g_sq0[i] = 0.f; }
    if (i < H1) { g_sum1[i] = 0.f; g_sq1[i] = 0.f; }
    if (i < H2) { g_sum2[i] = 0.f; g_sq2[i] = 0.f; }
}

__global__ void count_kernel(const int* __restrict__ src, const int* __restrict__ dst, int n) {
    int i = blockIdx.x * blockDim.x + threadIdx.x;
    if (i < n) {
        atomicAdd(&g_cnt_src[src[i]], 1);
        atomicAdd(&g_cnt_dst[dst[i]], 1);
    }
}

// split h into fp16 hi/lo planes (also feeds the GEMM1 gather path)
__global__ void hsplit_kernel(const float* __restrict__ h, int n4) {
    int i = blockIdx.x * blockDim.x + threadIdx.x;
    if (i < n4) {
        float4 v = ((const float4*)h)[i];
        uint32_t h0, l0, h1, l1;
        split_pair_h(v.x, v.y, h0, l0);
        split_pair_h(v.z, v.w, h1, l1);
        ((uint2*)g_h2h)[i] = make_uint2(h0, h1);
        ((uint2*)g_h2l)[i] = make_uint2(l0, l1);
    }
}

// degree-weighted BN0 stats for h parts; 64 nodes/block -> wide grid, good occupancy
#define NPB 64
__global__ void hstats_kernel(const float* __restrict__ h, int n_nodes) {
    __shared__ float c1s[NPB], c2s[NPB];
    int t  = threadIdx.x;
    int v0 = blockIdx.x * NPB;
    if (t < NPB) {
        int v = v0 + t;
        c1s[t] = (v < n_nodes) ? (float)g_cnt_src[v] : 0.f;
        c2s[t] = (v < n_nodes) ? (float)g_cnt_dst[v] : 0.f;
    }
    __syncthreads();
    float s1 = 0.f, q1 = 0.f, s2 = 0.f, q2 = 0.f;
    int lim = n_nodes - v0; if (lim > NPB) lim = NPB;
    for (int i = 0; i < lim; i++) {
        float x  = h[(long)(v0 + i) * D_H + t];
        float x2 = x * x;
        s1 += c1s[i] * x; q1 += c1s[i] * x2;
        s2 += c2s[i] * x; q2 += c2s[i] * x2;
    }
    atomicAdd(&g_sum0[t], s1);          atomicAdd(&g_sq0[t], q1);
    atomicAdd(&g_sum0[D_H + t], s2);    atomicAdd(&g_sq0[D_H + t], q2);
}

// e column stats fused with fp16 hi/lo plane split (single read of e)
__global__ void estats_kernel(const float* __restrict__ e, int M) {
    __shared__ float ss[4][64], sq_[4][64];
    int t = threadIdx.x & 63, r = threadIdx.x >> 6;
    long stride = (long)gridDim.x * 4;
    float sA = 0, qA = 0;
    for (long row = (long)blockIdx.x * 4 + r; row < M; row += stride) {
        float x = e[row * D_E + t];
        sA += x; qA += x * x;
        __half hh = __float2half_rn(x);
        g_e2h[row * D_E + t] = hh;
        g_e2l[row * D_E + t] = __float2half_rn(x - __half2float(hh));
    }
    ss[r][t] = sA; sq_[r][t] = qA;
    __syncthreads();
    if (threadIdx.x < 64) {
        float S = ss[0][t] + ss[1][t] + ss[2][t] + ss[3][t];
        float Q = sq_[0][t] + sq_[1][t] + sq_[2][t] + sq_[3][t];
        atomicAdd(&g_sum0[2 * D_H + t], S);
        atomicAdd(&g_sq0 [2 * D_H + t], Q);
    }
}

__global__ void affine_kernel(const float* __restrict__ sum, const float* __restrict__ sq,
                              const float* __restrict__ g, const float* __restrict__ b,
                              float* __restrict__ scale, float* __restrict__ shift,
                              int K, float invM) {
    int j = blockIdx.x * blockDim.x + threadIdx.x;
    if (j < K) {
        float mean = sum[j] * invM;
        float var  = sq[j] * invM - mean * mean;
        float sc   = g[j] * rsqrtf(var + 1e-5f);
        scale[j] = sc;
        shift[j] = b[j] - mean * sc;
    }
}

__global__ void foldW_kernel(const float* __restrict__ W, const float* __restrict__ scale,
                             __half* __restrict__ Wh, int N, int K) {
    int idx = blockIdx.x * blockDim.x + threadIdx.x;
    if (idx < N * K) {
        int k = idx % K;
        Wh[idx] = __float2half(W[idx] * scale[k]);
    }
}

__global__ void foldB_kernel(const float* __restrict__ W, const float* __restrict__ bvec,
                             const float* __restrict__ shift, float* __restrict__ bout, int K) {
    int o = blockIdx.x, t = threadIdx.x;
    float s = 0.f;
    for (int j = t; j < K; j += 128) s += W[(long)o * K + j] * shift[j];
    __shared__ float red[128];
    red[t] = s; __syncthreads();
    for (int w = 64; w > 0; w >>= 1) { if (t < w) red[t] += red[t + w]; __syncthreads(); }
    if (t == 0) bout[o] = bvec[o] + red[0];
}

__global__ void fold3_kernel(const float* __restrict__ W3, const float* __restrict__ b3) {
    int t = threadIdx.x;
    float w = W3[t];
    g_W3f[t] = w * g_scale2[t];
    __shared__ float red[128];
    red[t] = w * g_shift2[t]; __syncthreads();
    for (int w2 = 64; w2 > 0; w2 >>= 1) { if (t < w2) red[t] += red[t + w2]; __syncthreads(); }
    if (t == 0) g_b3f[0] = b3[0] + red[0];
}

__global__ void out_kernel(const float* __restrict__ Y2, float* __restrict__ out, int M) {
    int warp = (blockIdx.x * blockDim.x + threadIdx.x) >> 5;
    int lane = threadIdx.x & 31;
    if (warp >= M) return;
    float4 v = ((const float4*)(Y2 + (long)warp * H2))[lane];
    int c = lane * 4;
    float s = v.x * g_W3f[c] + v.y * g_W3f[c + 1] + v.z * g_W3f[c + 2] + v.w * g_W3f[c + 3];
    #pragma unroll
    for (int o = 16; o > 0; o >>= 1) s += __shfl_down_sync(0xffffffffu, s, o);
    if (lane == 0) out[warp] = s + g_b3f[0];
}

// ======================= mma.sync fp16x2 GEMM, cp.async pipeline ==================
// Y[m][n] = relu( sum_k A[m][k]*B[n][k] + bias[n] )
// A as fp16 hi+lo planes (pre-split; exact to ~2^-22), B single fp16 plane.
// cp.async 2-stage double buffer (96KB), 2 CTAs/SM (192KB total): one CTA's MMA
// phase hides the other's barrier/ldsm latency. No register prefetch -> no spill
// under the 128-reg occ-2 cap (R11's failure mode removed by R12's cp.async).

template<bool GATHER, int KTOT, int NTOT, bool OUTPAIR>
__global__ void __launch_bounds__(256, 2)
gemm_mma_kernel(const __half* __restrict__ Hh, const __half* __restrict__ Hl,
                const __half* __restrict__ Eh, const __half* __restrict__ El,
                const int* __restrict__ srcv, const int* __restrict__ dstv,
                const __half* __restrict__ Bh,
                const float* __restrict__ bias,
                __half* __restrict__ Yh, __half* __restrict__ Yl,
                float* __restrict__ Yf,
                float* __restrict__ sumP, float* __restrict__ sqP)
{
    constexpr int NCH = KTOT / 64;
    constexpr int PSZ = 128 * 128;     // bytes per plane (128 rows x 128B)
    constexpr int STG = 3 * PSZ;       // stage = Ah + Al + Bh planes

    extern __shared__ char smem[];
    __shared__ int s_src[128], s_dst[128];
    __shared__ float s_sum[128], s_sq[128];

    const uint32_t sbase = smem_to_u32(smem);

    int tid = threadIdx.x, lane = tid & 31, warp = tid >> 5;
    int wm = warp >> 1, wn = warp & 1;
    long m0 = (long)blockIdx.y * 128;
    int  n0 = blockIdx.x * 128;

    const char* Bbase = (const char*)(Bh + (long)n0 * KTOT);

    if (tid < 128) { s_sum[tid] = 0.f; s_sq[tid] = 0.f; }
    if (GATHER) {
        if (tid < 128) s_src[tid] = srcv[m0 + tid];
        else           s_dst[tid - 128] = dstv[m0 + (tid - 128)];
    }
    __syncthreads();

    int rowA = tid >> 1, hfA = tid & 1;

    // issue all cp.asyncs for chunk c into stage c&1
    auto issue_chunk = [&](int c) {
        uint32_t sb = sbase + (uint32_t)(c & 1) * STG;
        const char *srcAh, *srcAl;
        if (GATHER) {
            if (c < 4) {
                int node = (c < 2) ? s_src[rowA] : s_dst[rowA];
                long off = (long)node * (D_H * 2) + (c & 1) * 128 + hfA * 64;
                srcAh = (const char*)Hh + off;
                srcAl = (const char*)Hl + off;
            } else {
                long off = (m0 + rowA) * (D_E * 2) + hfA * 64;
                srcAh = (const char*)Eh + off;
                srcAl = (const char*)El + off;
            }
        } else {
            long off = ((m0 + rowA) * KTOT + c * 64) * 2 + hfA * 64;
            srcAh = (const char*)Hh + off;   // y1 hi plane
            srcAl = (const char*)Hl + off;   // y1 lo plane
        }
        #pragma unroll
        for (int j = 0; j < 4; j++) {
            uint32_t o = SWZ((uint32_t)(rowA * 128 + hfA * 64 + j * 16));
            cp16(sb + o,       srcAh + j * 16);
            cp16(sb + PSZ + o, srcAl + j * 16);
        }
        const char* srcB = Bbase + ((long)rowA * KTOT + c * 64) * 2 + hfA * 64;
        #pragma unroll
        for (int j = 0; j < 4; j++) {
            uint32_t o = SWZ((uint32_t)(rowA * 128 + hfA * 64 + j * 16));
            cp16(sb + 2 * PSZ + o, srcB + j * 16);
        }
    };

    float acc[2][8][4];
    #pragma unroll
    for (int i = 0; i < 2; i++)
        #pragma unroll
        for (int j = 0; j < 8; j++)
            #pragma unroll
            for (int q = 0; q < 4; q++) acc[i][j][q] = 0.f;

    issue_chunk(0); CP_COMMIT();

    for (int c = 0; c < NCH; c++) {
        if (c + 1 < NCH) { issue_chunk(c + 1); CP_COMMIT(); CP_WAIT1(); }
        else             { CP_WAIT0(); }
        __syncthreads();

        uint32_t sb = sbase + (uint32_t)(c & 1) * STG;
        uint32_t sAh = sb, sAl = sb + PSZ, sBh = sb + 2 * PSZ;

        #pragma unroll
        for (int kk = 0; kk < 4; kk++) {
            uint32_t ah[2][4], al[2][4], bh[4][4];
            uint32_t colb = (uint32_t)(kk * 32 + ((lane >> 4) << 4));
            int rA = wm * 32 + (lane & 15);
            #pragma unroll
            for (int mt = 0; mt < 2; mt++) {
                uint32_t off = SWZ((uint32_t)((rA + mt * 16) * 128) + colb);
                ldsm4(ah[mt], sAh + off);
                ldsm4(al[mt], sAl + off);
            }
            int rB = wn * 64 + (lane & 15);
            #pragma unroll
            for (int q = 0; q < 4; q++) {
                uint32_t off = SWZ((uint32_t)((rB + q * 16) * 128) + colb);
                ldsm4(bh[q], sBh + off);
            }
            // hi * B
            #pragma unroll
            for (int mt = 0; mt < 2; mt++)
                #pragma unroll
                for (int q = 0; q < 4; q++) {
                    mma_f16(acc[mt][2*q],   ah[mt], bh[q][0], bh[q][2]);
                    mma_f16(acc[mt][2*q+1], ah[mt], bh[q][1], bh[q][3]);
                }
            // lo * B
            #pragma unroll
            for (int mt = 0; mt < 2; mt++)
                #pragma unroll
                for (int q = 0; q < 4; q++) {
                    mma_f16(acc[mt][2*q],   al[mt], bh[q][0], bh[q][2]);
                    mma_f16(acc[mt][2*q+1], al[mt], bh[q][1], bh[q][3]);
                }
        }
        __syncthreads();
    }

    // ===== epilogue =====
    int lane4 = lane >> 2, lanem = lane & 3;

    #pragma unroll
    for (int nt = 0; nt < 8; nt++) {
        int col = wn * 64 + nt * 8 + lanem * 2;
        float b0v = __ldg(&bias[n0 + col]), b1v = __ldg(&bias[n0 + col + 1]);
        #pragma unroll
        for (int mt = 0; mt < 2; mt++) {
            acc[mt][nt][0] = fmaxf(acc[mt][nt][0] + b0v, 0.f);
            acc[mt][nt][1] = fmaxf(acc[mt][nt][1] + b1v, 0.f);
            acc[mt][nt][2] = fmaxf(acc[mt][nt][2] + b0v, 0.f);
            acc[mt][nt][3] = fmaxf(acc[mt][nt][3] + b1v, 0.f);
        }
    }

    // fused column stats
    {
        float ps[16], pq[16];
        #pragma unroll
        for (int nt = 0; nt < 8; nt++) {
            float s0 = acc[0][nt][0] + acc[0][nt][2] + acc[1][nt][0] + acc[1][nt][2];
            float s1 = acc[0][nt][1] + acc[0][nt][3] + acc[1][nt][1] + acc[1][nt][3];
            float q0 = acc[0][nt][0]*acc[0][nt][0] + acc[0][nt][2]*acc[0][nt][2]
                     + acc[1][nt][0]*acc[1][nt][0] + acc[1][nt][2]*acc[1][nt][2];
            float q1 = acc[0][nt][1]*acc[0][nt][1] + acc[0][nt][3]*acc[0][nt][3]
                     + acc[1][nt][1]*acc[1][nt][1] + acc[1][nt][3]*acc[1][nt][3];
            ps[2*nt] = s0; ps[2*nt+1] = s1; pq[2*nt] = q0; pq[2*nt+1] = q1;
        }
        #pragma unroll
        for (int j = 0; j < 16; j++) {
            #pragma unroll
            for (int o = 4; o < 32; o <<= 1) {
                ps[j] += __shfl_xor_sync(0xffffffffu, ps[j], o);
                pq[j] += __shfl_xor_sync(0xffffffffu, pq[j], o);
            }
        }
        if (lane4 == 0) {
            #pragma unroll
            for (int j = 0; j < 16; j++) {
                int col = wn * 64 + (j >> 1) * 8 + lanem * 2 + (j & 1);
                atomicAdd(&s_sum[col], ps[j]);
                atomicAdd(&s_sq[col],  pq[j]);
            }
        }
    }

    __syncthreads();

    if (OUTPAIR) {
        constexpr int RS = 68;   // u32 row stride (272B, 16B aligned)
        uint32_t* st = (uint32_t*)smem;
        #pragma unroll
        for (int mt = 0; mt < 2; mt++) {
            int r0l = wm * 32 + mt * 16 + lane4;
            #pragma unroll
            for (int nt = 0; nt < 8; nt++) {
                int cp = wn * 32 + nt * 4 + lanem;
                uint32_t hi, lo;
                split_pair_h(acc[mt][nt][0], acc[mt][nt][1], hi, lo);
                st[r0l * RS + cp] = hi;
                st[128 * RS + r0l * RS + cp] = lo;
                split_pair_h(acc[mt][nt][2], acc[mt][nt][3], hi, lo);
                st[(r0l + 8) * RS + cp] = hi;
                st[128 * RS + (r0l + 8) * RS + cp] = lo;
            }
        }
        __syncthreads();
        int l16 = tid & 15, rq = tid >> 4;
        uint32_t* dsts[2] = { (uint32_t*)Yh, (uint32_t*)Yl };
        #pragma unroll
        for (int p = 0; p < 2; p++) {
            #pragma unroll
            for (int it = 0; it < 8; it++) {
                int rowi = it * 16 + rq;
                uint4 v = *(uint4*)&st[p * 128 * RS + rowi * RS + l16 * 4];
                *(uint4*)&dsts[p][(m0 + rowi) * (NTOT / 2) + (n0 >> 1) + l16 * 4] = v;
            }
        }
    } else {
        constexpr int RS = 132;
        float* st = (float*)smem;
        #pragma unroll
        for (int mt = 0; mt < 2; mt++) {
            int r0l = wm * 32 + mt * 16 + lane4;
            #pragma unroll
            for (int nt = 0; nt < 8; nt++) {
                int col = wn * 64 + nt * 8 + lanem * 2;
                st[r0l * RS + col]           = acc[mt][nt][0];
                st[r0l * RS + col + 1]       = acc[mt][nt][1];
                st[(r0l + 8) * RS + col]     = acc[mt][nt][2];
                st[(r0l + 8) * RS + col + 1] = acc[mt][nt][3];
            }
        }
        __syncthreads();
        int l32 = tid & 31, rq = tid >> 5;
        #pragma unroll
        for (int it = 0; it < 16; it++) {
            int rowi = it * 8 + rq;
            float4 v = *(float4*)&st[rowi * RS + l32 * 4];
            *(float4*)&Yf[(m0 + rowi) * NTOT + l32 * 4] = v;
        }
    }

    if (tid < 128) {
        atomicAdd(&sumP[n0 + tid], s_sum[tid]);
        atomicAdd(&sqP[n0 + tid],  s_sq[tid]);
    }
}

// ======================= host launch sequence =====================================
extern "C" void kernel_launch(void* const* d_in, const int* in_sizes, int n_in,
                              void* d_out, int out_size) {
    const float* h     = (const float*)d_in[0];
    const float* e     = (const float*)d_in[1];
    const int*   src   = (const int*)  d_in[2];
    const int*   dst   = (const int*)  d_in[3];
    const float* bn0_g = (const float*)d_in[4];
    const float* bn0_b = (const float*)d_in[5];
    const float* W1    = (const float*)d_in[6];
    const float* b1    = (const float*)d_in[7];
    const float* bn1_g = (const float*)d_in[8];
    const float* bn1_b = (const float*)d_in[9];
    const float* W2    = (const float*)d_in[10];
    const float* b2    = (const float*)d_in[11];
    const float* bn2_g = (const float*)d_in[12];
    const float* bn2_b = (const float*)d_in[13];
    const float* W3    = (const float*)d_in[14];
    const float* b3    = (const float*)d_in[15];
    float* out = (float*)d_out;

    int n_nodes = in_sizes[0] / D_H;
    int n_edges = in_sizes[2];
    float invM = 1.0f / (float)n_edges;
    int ntiles = n_edges / 128;

    __half *h2h, *h2l, *e2h, *e2l, *y1h, *y1l, *w1h, *w2h;
    float *y2f;
    float *sum0, *sq0, *sum1, *sq1, *sum2, *sq2;
    float *scale0, *shift0, *scale1, *shift1, *scale2, *shift2, *b1f, *b2f;
    cudaGetSymbolAddress((void**)&h2h, g_h2h);
    cudaGetSymbolAddress((void**)&h2l, g_h2l);
    cudaGetSymbolAddress((void**)&e2h, g_e2h);
    cudaGetSymbolAddress((void**)&e2l, g_e2l);
    cudaGetSymbolAddress((void**)&y1h, g_y1h);
    cudaGetSymbolAddress((void**)&y1l, g_y1l);
    cudaGetSymbolAddress((void**)&y2f, g_y2f);
    cudaGetSymbolAddress((void**)&w1h, g_W1h);
    cudaGetSymbolAddress((void**)&w2h, g_W2h);
    cudaGetSymbolAddress((void**)&sum0, g_sum0);
    cudaGetSymbolAddress((void**)&sq0,  g_sq0);
    cudaGetSymbolAddress((void**)&sum1, g_sum1);
    cudaGetSymbolAddress((void**)&sq1,  g_sq1);
    cudaGetSymbolAddress((void**)&sum2, g_sum2);
    cudaGetSymbolAddress((void**)&sq2,  g_sq2);
    cudaGetSymbolAddress((void**)&scale0, g_scale0);
    cudaGetSymbolAddress((void**)&shift0, g_shift0);
    cudaGetSymbolAddress((void**)&scale1, g_scale1);
    cudaGetSymbolAddress((void**)&shift1, g_shift1);
    cudaGetSymbolAddress((void**)&scale2, g_scale2);
    cudaGetSymbolAddress((void**)&shift2, g_shift2);
    cudaGetSymbolAddress((void**)&b1f, g_b1f);
    cudaGetSymbolAddress((void**)&b2f, g_b2f);

    // 2-stage double buffer: 96KB/CTA; occ-2 -> 192KB/SM
    constexpr int SMEM_SZ = 2 * 3 * 128 * 128;   // 98304
    cudaFuncSetAttribute((const void*)gemm_mma_kernel<true, 320, 256, true>,
                         cudaFuncAttributeMaxDynamicSharedMemorySize, SMEM_SZ);
    cudaFuncSetAttribute((const void*)gemm_mma_kernel<false, 256, 128, false>,
                         cudaFuncAttributeMaxDynamicSharedMemorySize, SMEM_SZ);

    // 1) BN0 stats + operand pre-split (h planes, e planes fused into estats)
    zero_kernel<<<(n_nodes + 255) / 256, 256>>>(n_nodes);
    count_kernel<<<(n_edges + 255) / 256, 256>>>(src, dst, n_edges);
    hsplit_kernel<<<(n_nodes * D_H / 4 + 255) / 256, 256>>>(h, n_nodes * D_H / 4);
    hstats_kernel<<<(n_nodes + NPB - 1) / NPB, 128>>>(h, n_nodes);
    estats_kernel<<<2048, 256>>>(e, n_edges);
    affine_kernel<<<(F0 + 127) / 128, 128>>>(sum0, sq0, bn0_g, bn0_b, scale0, shift0, F0, invM);

    // 2) fold BN0 into W1 (single fp16 plane) + bias
    foldW_kernel<<<(H1 * F0 + 255) / 256, 256>>>(W1, scale0, w1h, H1, F0);
    foldB_kernel<<<H1, 128>>>(W1, b1, shift0, b1f, F0);

    // 3) GEMM1: y1 = relu(gather(x) @ W1f^T + b1f); fp16 pair out; stats fused.
    gemm_mma_kernel<true, 320, 256, true><<<dim3(2, ntiles), 256, SMEM_SZ>>>(
        h2h, h2l, e2h, e2l, src, dst, w1h, b1f, y1h, y1l, nullptr, sum1, sq1);

    // 4) BN1 affine + fold into W2
    affine_kernel<<<(H1 + 127) / 128, 128>>>(sum1, sq1, bn1_g, bn1_b, scale1, shift1, H1, invM);
    foldW_kernel<<<(H2 * H1 + 255) / 256, 256>>>(W2, scale1, w2h, H2, H1);
    foldB_kernel<<<H2, 128>>>(W2, b2, shift1, b2f, H1);

    // 5) GEMM2: y2 = relu(y1 @ W2f^T + b2f), fp32 out; stats fused.
    gemm_mma_kernel<false, 256, 128, false><<<dim3(1, ntiles), 256, SMEM_SZ>>>(
        y1h, y1l, nullptr, nullptr, nullptr, nullptr, w2h, b2f,
        nullptr, nullptr, y2f, sum2, sq2);

    // 6) BN2 affine + fold into W3, final matvec
    affine_kernel<<<1, 128>>>(sum2, sq2, bn2_g, bn2_b, scale2, shift2, H2, invM);
    fold3_kernel<<<1, 128>>>(W3, b3);
    out_kernel<<<(n_edges + 7) / 8, 256>>>(y2f, out, n_edges);
}

// round 17
// speedup vs baseline: 1.5323x; 1.5323x over previous
#include <cuda_runtime.h>
#include <cuda_fp16.h>
#include <cstdint>
#include <math.h>

#define D_H   128
#define D_E   64
#define F0    320
#define H1    256
#define H2    128
#define MAX_NODES 50000
#define MAX_EDGES 800000

// ======================= helpers ==================================================
__device__ __forceinline__ uint32_t smem_to_u32(const void* p) {
    uint32_t a;
    asm("{ .reg .u64 t; cvta.to.shared.u64 t, %1; cvt.u32.u64 %0, t; }" : "=r"(a) : "l"(p));
    return a;
}
#define SWZ(off) ((off) ^ (((off) >> 3) & 0x70))

__device__ __forceinline__ void ldsm4(uint32_t* r, uint32_t addr) {
    asm volatile("ldmatrix.sync.aligned.m8n8.x4.shared.b16 {%0,%1,%2,%3}, [%4];"
                 : "=r"(r[0]), "=r"(r[1]), "=r"(r[2]), "=r"(r[3]) : "r"(addr));
}
__device__ __forceinline__ void mma_f16(float* d, const uint32_t* a, uint32_t b0, uint32_t b1) {
    asm volatile("mma.sync.aligned.m16n8k16.row.col.f32.f16.f16.f32 "
                 "{%0,%1,%2,%3}, {%4,%5,%6,%7}, {%8,%9}, {%0,%1,%2,%3};"
                 : "+f"(d[0]), "+f"(d[1]), "+f"(d[2]), "+f"(d[3])
                 : "r"(a[0]), "r"(a[1]), "r"(a[2]), "r"(a[3]), "r"(b0), "r"(b1));
}
__device__ __forceinline__ uint32_t pack_h2(float x, float y) {
    __half2 h = __floats2half2_rn(x, y);
    return *reinterpret_cast<uint32_t*>(&h);
}
__device__ __forceinline__ void cp16(uint32_t smem_dst, const void* gmem_src) {
    asm volatile("cp.async.ca.shared.global [%0], [%1], 16;"
                 :: "r"(smem_dst), "l"(gmem_src));
}
#define CP_COMMIT() asm volatile("cp.async.commit_group;" ::: "memory")
#define CP_WAIT1()  asm volatile("cp.async.wait_group 1;" ::: "memory")
#define CP_WAIT0()  asm volatile("cp.async.wait_group 0;" ::: "memory")

// ======================= device scratch ==========================================
__device__ __half g_h2h[(size_t)MAX_NODES * D_H];   // h in fp16
__device__ __half g_e2h[(size_t)MAX_EDGES * D_E];   // e in fp16
__device__ __half g_y1h[(size_t)MAX_EDGES * H1];    // y1 in fp16
__device__ float  g_y2f[(size_t)MAX_EDGES * H2];
__device__ __half g_W1h[H1 * F0];
__device__ __half g_W2h[H2 * H1];
__device__ int   g_cnt_src[MAX_NODES];
__device__ int   g_cnt_dst[MAX_NODES];
__device__ float g_sum0[F0], g_sq0[F0];
__device__ float g_sum1[H1], g_sq1[H1];
__device__ float g_sum2[H2], g_sq2[H2];
__device__ float g_scale0[F0], g_shift0[F0];
__device__ float g_scale1[H1], g_shift1[H1];
__device__ float g_scale2[H2], g_shift2[H2];
__device__ float g_b1f[H1], g_b2f[H2];
__device__ float g_W3f[H2];
__device__ float g_b3f[1];

// ======================= setup / stats kernels ===================================
__global__ void zero_kernel(int n_nodes) {
    int i = blockIdx.x * blockDim.x + threadIdx.x;
    if (i < n_nodes) { g_cnt_src[i] = 0; g_cnt_dst[i] = 0; }
    if (i < F0) { g_sum0[i] = 0.f; g_sq0[i] = 0.f; }
    if (i < H1) { g_sum1[i] = 0.f; g_sq1[i] = 0.f; }
    if (i < H2) { g_sum2[i] = 0.f; g_sq2[i] = 0.f; }
}

__global__ void count_kernel(const int* __restrict__ src, const int* __restrict__ dst, int n) {
    int i = blockIdx.x * blockDim.x + threadIdx.x;
    if (i < n) {
        atomicAdd(&g_cnt_src[src[i]], 1);
        atomicAdd(&g_cnt_dst[dst[i]], 1);
    }
}

// h -> fp16 plane
__global__ void hconv_kernel(const float* __restrict__ h, int n4) {
    int i = blockIdx.x * blockDim.x + threadIdx.x;
    if (i < n4) {
        float4 v = ((const float4*)h)[i];
        ((uint2*)g_h2h)[i] = make_uint2(pack_h2(v.x, v.y), pack_h2(v.z, v.w));
    }
}

// degree-weighted BN0 stats for h parts; 64 nodes/block -> wide grid
#define NPB 64
__global__ void hstats_kernel(const float* __restrict__ h, int n_nodes) {
    __shared__ float c1s[NPB], c2s[NPB];
    int t  = threadIdx.x;
    int v0 = blockIdx.x * NPB;
    if (t < NPB) {
        int v = v0 + t;
        c1s[t] = (v < n_nodes) ? (float)g_cnt_src[v] : 0.f;
        c2s[t] = (v < n_nodes) ? (float)g_cnt_dst[v] : 0.f;
    }
    __syncthreads();
    float s1 = 0.f, q1 = 0.f, s2 = 0.f, q2 = 0.f;
    int lim = n_nodes - v0; if (lim > NPB) lim = NPB;
    for (int i = 0; i < lim; i++) {
        float x  = h[(long)(v0 + i) * D_H + t];
        float x2 = x * x;
        s1 += c1s[i] * x; q1 += c1s[i] * x2;
        s2 += c2s[i] * x; q2 += c2s[i] * x2;
    }
    atomicAdd(&g_sum0[t], s1);          atomicAdd(&g_sq0[t], q1);
    atomicAdd(&g_sum0[D_H + t], s2);    atomicAdd(&g_sq0[D_H + t], q2);
}

// e column stats fused with fp16 conversion (single read of e)
__global__ void estats_kernel(const float* __restrict__ e, int M) {
    __shared__ float ss[4][64], sq_[4][64];
    int t = threadIdx.x & 63, r = threadIdx.x >> 6;
    long stride = (long)gridDim.x * 4;
    float sA = 0, qA = 0;
    for (long row = (long)blockIdx.x * 4 + r; row < M; row += stride) {
        float x = e[row * D_E + t];
        sA += x; qA += x * x;
        g_e2h[row * D_E + t] = __float2half_rn(x);
    }
    ss[r][t] = sA; sq_[r][t] = qA;
    __syncthreads();
    if (threadIdx.x < 64) {
        float S = ss[0][t] + ss[1][t] + ss[2][t] + ss[3][t];
        float Q = sq_[0][t] + sq_[1][t] + sq_[2][t] + sq_[3][t];
        atomicAdd(&g_sum0[2 * D_H + t], S);
        atomicAdd(&g_sq0 [2 * D_H + t], Q);
    }
}

__global__ void affine_kernel(const float* __restrict__ sum, const float* __restrict__ sq,
                              const float* __restrict__ g, const float* __restrict__ b,
                              float* __restrict__ scale, float* __restrict__ shift,
                              int K, float invM) {
    int j = blockIdx.x * blockDim.x + threadIdx.x;
    if (j < K) {
        float mean = sum[j] * invM;
        float var  = sq[j] * invM - mean * mean;
        float sc   = g[j] * rsqrtf(var + 1e-5f);
        scale[j] = sc;
        shift[j] = b[j] - mean * sc;
    }
}

__global__ void foldW_kernel(const float* __restrict__ W, const float* __restrict__ scale,
                             __half* __restrict__ Wh, int N, int K) {
    int idx = blockIdx.x * blockDim.x + threadIdx.x;
    if (idx < N * K) {
        int k = idx % K;
        Wh[idx] = __float2half(W[idx] * scale[k]);
    }
}

__global__ void foldB_kernel(const float* __restrict__ W, const float* __restrict__ bvec,
                             const float* __restrict__ shift, float* __restrict__ bout, int K) {
    int o = blockIdx.x, t = threadIdx.x;
    float s = 0.f;
    for (int j = t; j < K; j += 128) s += W[(long)o * K + j] * shift[j];
    __shared__ float red[128];
    red[t] = s; __syncthreads();
    for (int w = 64; w > 0; w >>= 1) { if (t < w) red[t] += red[t + w]; __syncthreads(); }
    if (t == 0) bout[o] = bvec[o] + red[0];
}

__global__ void fold3_kernel(const float* __restrict__ W3, const float* __restrict__ b3) {
    int t = threadIdx.x;
    float w = W3[t];
    g_W3f[t] = w * g_scale2[t];
    __shared__ float red[128];
    red[t] = w * g_shift2[t]; __syncthreads();
    for (int w2 = 64; w2 > 0; w2 >>= 1) { if (t < w2) red[t] += red[t + w2]; __syncthreads(); }
    if (t == 0) g_b3f[0] = b3[0] + red[0];
}

__global__ void out_kernel(const float* __restrict__ Y2, float* __restrict__ out, int M) {
    int warp = (blockIdx.x * blockDim.x + threadIdx.x) >> 5;
    int lane = threadIdx.x & 31;
    if (warp >= M) return;
    float4 v = ((const float4*)(Y2 + (long)warp * H2))[lane];
    int c = lane * 4;
    float s = v.x * g_W3f[c] + v.y * g_W3f[c + 1] + v.z * g_W3f[c + 2] + v.w * g_W3f[c + 3];
    #pragma unroll
    for (int o = 16; o > 0; o >>= 1) s += __shfl_down_sync(0xffffffffu, s, o);
    if (lane == 0) out[warp] = s + g_b3f[0];
}

// ======================= mma.sync fp16 GEMM, cp.async pipeline ====================
// Y[m][n] = relu( sum_k A[m][k]*B[n][k] + bias[n] ), all operands single fp16.
// cp.async 2-stage double buffer (2 x 32KB), occ-1 (HMMA pipe-bound per R12/R14
// evidence; occ-2 measured neutral-negative twice).
// GATHER: A rows from fp16 node planes (src/dst) + fp16 edge rows.
// Epilogue: fused column sum/sumsq (fp32 accumulators) + smem-staged stores.
// OUTHALF: fp16 plane out (y1); else fp32 plane out (y2).

template<bool GATHER, int KTOT, int NTOT, bool OUTHALF>
__global__ void __launch_bounds__(256, 1)
gemm_mma_kernel(const __half* __restrict__ Ain, const __half* __restrict__ Eh,
                const int* __restrict__ srcv, const int* __restrict__ dstv,
                const __half* __restrict__ Bh,
                const float* __restrict__ bias,
                __half* __restrict__ Yh, float* __restrict__ Yf,
                float* __restrict__ sumP, float* __restrict__ sqP)
{
    constexpr int NCH = KTOT / 64;
    constexpr int PSZ = 128 * 128;     // bytes per plane (128 rows x 128B)
    constexpr int STG = 2 * PSZ;       // stage = A + B planes

    extern __shared__ char smem[];
    __shared__ int s_src[128], s_dst[128];
    __shared__ float s_sum[128], s_sq[128];

    const uint32_t sbase = smem_to_u32(smem);

    int tid = threadIdx.x, lane = tid & 31, warp = tid >> 5;
    int wm = warp >> 1, wn = warp & 1;
    long m0 = (long)blockIdx.y * 128;
    int  n0 = blockIdx.x * 128;

    const char* Bbase = (const char*)(Bh + (long)n0 * KTOT);

    if (tid < 128) { s_sum[tid] = 0.f; s_sq[tid] = 0.f; }
    if (GATHER) {
        if (tid < 128) s_src[tid] = srcv[m0 + tid];
        else           s_dst[tid - 128] = dstv[m0 + (tid - 128)];
    }
    __syncthreads();

    int rowA = tid >> 1, hfA = tid & 1;

    // issue all cp.asyncs for chunk c into stage c&1
    auto issue_chunk = [&](int c) {
        uint32_t sb = sbase + (uint32_t)(c & 1) * STG;
        const char* srcA;
        if (GATHER) {
            if (c < 4) {
                int node = (c < 2) ? s_src[rowA] : s_dst[rowA];
                srcA = (const char*)Ain + (long)node * (D_H * 2) + (c & 1) * 128 + hfA * 64;
            } else {
                srcA = (const char*)Eh + (m0 + rowA) * (D_E * 2) + hfA * 64;
            }
        } else {
            srcA = (const char*)Ain + ((m0 + rowA) * KTOT + c * 64) * 2 + hfA * 64;
        }
        const char* srcB = Bbase + ((long)rowA * KTOT + c * 64) * 2 + hfA * 64;
        #pragma unroll
        for (int j = 0; j < 4; j++) {
            uint32_t o = SWZ((uint32_t)(rowA * 128 + hfA * 64 + j * 16));
            cp16(sb + o,       srcA + j * 16);
            cp16(sb + PSZ + o, srcB + j * 16);
        }
    };

    float acc[2][8][4];
    #pragma unroll
    for (int i = 0; i < 2; i++)
        #pragma unroll
        for (int j = 0; j < 8; j++)
            #pragma unroll
            for (int q = 0; q < 4; q++) acc[i][j][q] = 0.f;

    issue_chunk(0); CP_COMMIT();

    for (int c = 0; c < NCH; c++) {
        if (c + 1 < NCH) { issue_chunk(c + 1); CP_COMMIT(); CP_WAIT1(); }
        else             { CP_WAIT0(); }
        __syncthreads();

        uint32_t sb = sbase + (uint32_t)(c & 1) * STG;
        uint32_t sA = sb, sB = sb + PSZ;

        #pragma unroll
        for (int kk = 0; kk < 4; kk++) {
            uint32_t ah[2][4], bh[4][4];
            uint32_t colb = (uint32_t)(kk * 32 + ((lane >> 4) << 4));
            int rA = wm * 32 + (lane & 15);
            #pragma unroll
            for (int mt = 0; mt < 2; mt++) {
                uint32_t off = SWZ((uint32_t)((rA + mt * 16) * 128) + colb);
                ldsm4(ah[mt], sA + off);
            }
            int rB = wn * 64 + (lane & 15);
            #pragma unroll
            for (int q = 0; q < 4; q++) {
                uint32_t off = SWZ((uint32_t)((rB + q * 16) * 128) + colb);
                ldsm4(bh[q], sB + off);
            }
            #pragma unroll
            for (int mt = 0; mt < 2; mt++)
                #pragma unroll
                for (int q = 0; q < 4; q++) {
                    mma_f16(acc[mt][2*q],   ah[mt], bh[q][0], bh[q][2]);
                    mma_f16(acc[mt][2*q+1], ah[mt], bh[q][1], bh[q][3]);
                }
        }
        __syncthreads();
    }

    // ===== epilogue =====
    int lane4 = lane >> 2, lanem = lane & 3;

    #pragma unroll
    for (int nt = 0; nt < 8; nt++) {
        int col = wn * 64 + nt * 8 + lanem * 2;
        float b0v = __ldg(&bias[n0 + col]), b1v = __ldg(&bias[n0 + col + 1]);
        #pragma unroll
        for (int mt = 0; mt < 2; mt++) {
            acc[mt][nt][0] = fmaxf(acc[mt][nt][0] + b0v, 0.f);
            acc[mt][nt][1] = fmaxf(acc[mt][nt][1] + b1v, 0.f);
            acc[mt][nt][2] = fmaxf(acc[mt][nt][2] + b0v, 0.f);
            acc[mt][nt][3] = fmaxf(acc[mt][nt][3] + b1v, 0.f);
        }
    }

    // fused column stats (fp32 accumulators -> exact BN stats path)
    {
        float ps[16], pq[16];
        #pragma unroll
        for (int nt = 0; nt < 8; nt++) {
            float s0 = acc[0][nt][0] + acc[0][nt][2] + acc[1][nt][0] + acc[1][nt][2];
            float s1 = acc[0][nt][1] + acc[0][nt][3] + acc[1][nt][1] + acc[1][nt][3];
            float q0 = acc[0][nt][0]*acc[0][nt][0] + acc[0][nt][2]*acc[0][nt][2]
                     + acc[1][nt][0]*acc[1][nt][0] + acc[1][nt][2]*acc[1][nt][2];
            float q1 = acc[0][nt][1]*acc[0][nt][1] + acc[0][nt][3]*acc[0][nt][3]
                     + acc[1][nt][1]*acc[1][nt][1] + acc[1][nt][3]*acc[1][nt][3];
            ps[2*nt] = s0; ps[2*nt+1] = s1; pq[2*nt] = q0; pq[2*nt+1] = q1;
        }
        #pragma unroll
        for (int j = 0; j < 16; j++) {
            #pragma unroll
            for (int o = 4; o < 32; o <<= 1) {
                ps[j] += __shfl_xor_sync(0xffffffffu, ps[j], o);
                pq[j] += __shfl_xor_sync(0xffffffffu, pq[j], o);
            }
        }
        if (lane4 == 0) {
            #pragma unroll
            for (int j = 0; j < 16; j++) {
                int col = wn * 64 + (j >> 1) * 8 + lanem * 2 + (j & 1);
                atomicAdd(&s_sum[col], ps[j]);
                atomicAdd(&s_sq[col],  pq[j]);
            }
        }
    }

    __syncthreads();   // mainloop + stats done; stage memory free for staging

    if (OUTHALF) {
        constexpr int RS = 68;   // u32 row stride (272B, 16B aligned)
        uint32_t* st = (uint32_t*)smem;
        #pragma unroll
        for (int mt = 0; mt < 2; mt++) {
            int r0l = wm * 32 + mt * 16 + lane4;
            #pragma unroll
            for (int nt = 0; nt < 8; nt++) {
                int cp = wn * 32 + nt * 4 + lanem;
                st[r0l * RS + cp]       = pack_h2(acc[mt][nt][0], acc[mt][nt][1]);
                st[(r0l + 8) * RS + cp] = pack_h2(acc[mt][nt][2], acc[mt][nt][3]);
            }
        }
        __syncthreads();
        int l16 = tid & 15, rq = tid >> 4;       // 16 rows per iter
        uint32_t* dst = (uint32_t*)Yh;
        #pragma unroll
        for (int it = 0; it < 8; it++) {
            int rowi = it * 16 + rq;
            uint4 v = *(uint4*)&st[rowi * RS + l16 * 4];
            *(uint4*)&dst[(m0 + rowi) * (NTOT / 2) + (n0 >> 1) + l16 * 4] = v;
        }
    } else {
        constexpr int RS = 132;  // f32 row stride (528B, 16B aligned)
        float* st = (float*)smem;
        #pragma unroll
        for (int mt = 0; mt < 2; mt++) {
            int r0l = wm * 32 + mt * 16 + lane4;
            #pragma unroll
            for (int nt = 0; nt < 8; nt++) {
                int col = wn * 64 + nt * 8 + lanem * 2;
                st[r0l * RS + col]           = acc[mt][nt][0];
                st[r0l * RS + col + 1]       = acc[mt][nt][1];
                st[(r0l + 8) * RS + col]     = acc[mt][nt][2];
                st[(r0l + 8) * RS + col + 1] = acc[mt][nt][3];
            }
        }
        __syncthreads();
        int l32 = tid & 31, rq = tid >> 5;
        #pragma unroll
        for (int it = 0; it < 16; it++) {
            int rowi = it * 8 + rq;
            float4 v = *(float4*)&st[rowi * RS + l32 * 4];
            *(float4*)&Yf[(m0 + rowi) * NTOT + l32 * 4] = v;
        }
    }

    if (tid < 128) {
        atomicAdd(&sumP[n0 + tid], s_sum[tid]);
        atomicAdd(&sqP[n0 + tid],  s_sq[tid]);
    }
}

// ======================= host launch sequence =====================================
extern "C" void kernel_launch(void* const* d_in, const int* in_sizes, int n_in,
                              void* d_out, int out_size) {
    const float* h     = (const float*)d_in[0];
    const float* e     = (const float*)d_in[1];
    const int*   src   = (const int*)  d_in[2];
    const int*   dst   = (const int*)  d_in[3];
    const float* bn0_g = (const float*)d_in[4];
    const float* bn0_b = (const float*)d_in[5];
    const float* W1    = (const float*)d_in[6];
    const float* b1    = (const float*)d_in[7];
    const float* bn1_g = (const float*)d_in[8];
    const float* bn1_b = (const float*)d_in[9];
    const float* W2    = (const float*)d_in[10];
    const float* b2    = (const float*)d_in[11];
    const float* bn2_g = (const float*)d_in[12];
    const float* bn2_b = (const float*)d_in[13];
    const float* W3    = (const float*)d_in[14];
    const float* b3    = (const float*)d_in[15];
    float* out = (float*)d_out;

    int n_nodes = in_sizes[0] / D_H;
    int n_edges = in_sizes[2];
    float invM = 1.0f / (float)n_edges;
    int ntiles = n_edges / 128;

    __half *h2h, *e2h, *y1h, *w1h, *w2h;
    float *y2f;
    float *sum0, *sq0, *sum1, *sq1, *sum2, *sq2;
    float *scale0, *shift0, *scale1, *shift1, *scale2, *shift2, *b1f, *b2f;
    cudaGetSymbolAddress((void**)&h2h, g_h2h);
    cudaGetSymbolAddress((void**)&e2h, g_e2h);
    cudaGetSymbolAddress((void**)&y1h, g_y1h);
    cudaGetSymbolAddress((void**)&y2f, g_y2f);
    cudaGetSymbolAddress((void**)&w1h, g_W1h);
    cudaGetSymbolAddress((void**)&w2h, g_W2h);
    cudaGetSymbolAddress((void**)&sum0, g_sum0);
    cudaGetSymbolAddress((void**)&sq0,  g_sq0);
    cudaGetSymbolAddress((void**)&sum1, g_sum1);
    cudaGetSymbolAddress((void**)&sq1,  g_sq1);
    cudaGetSymbolAddress((void**)&sum2, g_sum2);
    cudaGetSymbolAddress((void**)&sq2,  g_sq2);
    cudaGetSymbolAddress((void**)&scale0, g_scale0);
    cudaGetSymbolAddress((void**)&shift0, g_shift0);
    cudaGetSymbolAddress((void**)&scale1, g_scale1);
    cudaGetSymbolAddress((void**)&shift1, g_shift1);
    cudaGetSymbolAddress((void**)&scale2, g_scale2);
    cudaGetSymbolAddress((void**)&shift2, g_shift2);
    cudaGetSymbolAddress((void**)&b1f, g_b1f);
    cudaGetSymbolAddress((void**)&b2f, g_b2f);

    // GEMM1: mainloop 2 stages x 32KB = 64KB (epilogue fp16 stage 34.8KB fits)
    // GEMM2: fp32 epilogue stage needs 67.6KB -> 67584
    constexpr int SMEM1 = 2 * 2 * 128 * 128;   // 65536
    constexpr int SMEM2 = 67584;
    cudaFuncSetAttribute((const void*)gemm_mma_kernel<true, 320, 256, true>,
                         cudaFuncAttributeMaxDynamicSharedMemorySize, SMEM1);
    cudaFuncSetAttribute((const void*)gemm_mma_kernel<false, 256, 128, false>,
                         cudaFuncAttributeMaxDynamicSharedMemorySize, SMEM2);

    // 1) BN0 stats + fp16 operand conversion (h plane, e plane fused into estats)
    zero_kernel<<<(n_nodes + 255) / 256, 256>>>(n_nodes);
    count_kernel<<<(n_edges + 255) / 256, 256>>>(src, dst, n_edges);
    hconv_kernel<<<(n_nodes * D_H / 4 + 255) / 256, 256>>>(h, n_nodes * D_H / 4);
    hstats_kernel<<<(n_nodes + NPB - 1) / NPB, 128>>>(h, n_nodes);
    estats_kernel<<<2048, 256>>>(e, n_edges);
    affine_kernel<<<(F0 + 127) / 128, 128>>>(sum0, sq0, bn0_g, bn0_b, scale0, shift0, F0, invM);

    // 2) fold BN0 into W1 (fp16) + bias
    foldW_kernel<<<(H1 * F0 + 255) / 256, 256>>>(W1, scale0, w1h, H1, F0);
    foldB_kernel<<<H1, 128>>>(W1, b1, shift0, b1f, F0);

    // 3) GEMM1: y1 = relu(gather(x) @ W1f^T + b1f); fp16 out; stats fused.
    gemm_mma_kernel<true, 320, 256, true><<<dim3(2, ntiles), 256, SMEM1>>>(
        h2h, e2h, src, dst, w1h, b1f, y1h, nullptr, sum1, sq1);

    // 4) BN1 affine + fold into W2
    affine_kernel<<<(H1 + 127) / 128, 128>>>(sum1, sq1, bn1_g, bn1_b, scale1, shift1, H1, invM);
    foldW_kernel<<<(H2 * H1 + 255) / 256, 256>>>(W2, scale1, w2h, H2, H1);
    foldB_kernel<<<H2, 128>>>(W2, b2, shift1, b2f, H1);

    // 5) GEMM2: y2 = relu(y1 @ W2f^T + b2f), fp32 out; stats fused.
    gemm_mma_kernel<false, 256, 128, false><<<dim3(1, ntiles), 256, SMEM2>>>(
        y1h, nullptr, nullptr, nullptr, w2h, b2f, nullptr, y2f, sum2, sq2);

    // 6) BN2 affine + fold into W3, final matvec
    affine_kernel<<<1, 128>>>(sum2, sq2, bn2_g, bn2_b, scale2, shift2, H2, invM);
    fold3_kernel<<<1, 128>>>(W3, b3);
    out_kernel<<<(n_edges + 7) / 8, 256>>>(y2f, out, n_edges);
}